// round 13
// baseline (speedup 1.0000x reference)
#include <cuda_runtime.h>
#include <cuda_fp16.h>
#include <cuda_bf16.h>
#include <cstdint>

#define N_NODES 50000
#define HD 128
#define E_MAX 600000

// ---------------- scratch (device globals; no dynamic allocation) ----------
__device__ float  g_dis[N_NODES];                 // rsqrt(degree incl. self-loop)
__device__ int    g_cnt[N_NODES];                 // in-degree histogram (zero-restored)
__device__ int    g_rowptr[N_NODES + 1];          // CSR row pointers
__device__ int    g_cursor[N_NODES];              // fill cursors
__device__ int    g_bsum[256];                    // scan block sums
__device__ int2   g_csr[E_MAX];                   // packed (src, norm), dst-sorted
__device__ __half g_xwh[(size_t)N_NODES * HD];    // x @ W^T (fp16)
__device__ float  g_h1[(size_t)N_NODES * HD];     // layer-1 output (fp32)

struct __align__(8) h4 { __half2 a, b; };

// Per-block index-width detection: int64 little-endian => odd 32-bit words of
// the first 256 logical elements are all zero (random indices: ~impossible).
// In-bounds for both interpretations (index 511 << 1.2M words).
static __device__ __forceinline__ int detect_is64_block(const int* __restrict__ ew) {
    __shared__ int found;
    if (threadIdx.x == 0) found = 0;
    __syncthreads();
    if (threadIdx.x < 256 && ew[2 * threadIdx.x + 1] != 0) found = 1;
    __syncthreads();
    return !found;
}

// ---------------- histogram (self-detecting) --------------------------------
__global__ void hist_kernel(const int* __restrict__ ew, int E) {
    int is64 = detect_is64_block(ew);
    int e = blockIdx.x * blockDim.x + threadIdx.x;
    if (e >= E) return;
    int d = is64 ? ew[2 * (E + e)] : ew[E + e];
    atomicAdd(&g_cnt[d], 1);
}

// ---- exclusive scan of g_cnt -> g_rowptr (3 kernels); also emits g_dis ----
__global__ void scanA_kernel(int n) {
    __shared__ int sm[256];
    int i = blockIdx.x * 256 + threadIdx.x;
    int v = (i < n) ? g_cnt[i] : 0;
    if (i < n) g_dis[i] = rsqrtf((float)(v + 1));
    sm[threadIdx.x] = v;
    __syncthreads();
    #pragma unroll
    for (int off = 1; off < 256; off <<= 1) {
        int t = (threadIdx.x >= off) ? sm[threadIdx.x - off] : 0;
        __syncthreads();
        sm[threadIdx.x] += t;
        __syncthreads();
    }
    if (i < n) g_rowptr[i] = sm[threadIdx.x] - v;
    if (threadIdx.x == 255) g_bsum[blockIdx.x] = sm[255];
}

__global__ void scanB_kernel(int nb) {
    __shared__ int sm[256];
    int v = (threadIdx.x < nb) ? g_bsum[threadIdx.x] : 0;
    sm[threadIdx.x] = v;
    __syncthreads();
    #pragma unroll
    for (int off = 1; off < 256; off <<= 1) {
        int t = (threadIdx.x >= off) ? sm[threadIdx.x - off] : 0;
        __syncthreads();
        sm[threadIdx.x] += t;
        __syncthreads();
    }
    if (threadIdx.x < nb) g_bsum[threadIdx.x] = sm[threadIdx.x] - v;
}

__global__ void scanC_kernel(int n, int E) {
    int i = blockIdx.x * 256 + threadIdx.x;
    if (i < n) {
        int rp = g_rowptr[i] + g_bsum[blockIdx.x];
        g_rowptr[i] = rp;
        g_cursor[i] = rp;
    }
    if (i == 0) g_rowptr[n] = E;
}

// ---------------- fill CSR (self-detecting; restores g_cnt to zero) --------
__global__ void fill_kernel(const int* __restrict__ ew, int E, int n) {
    int is64 = detect_is64_block(ew);
    int e = blockIdx.x * blockDim.x + threadIdx.x;
    if (e < E) {
        int s, d;
        if (is64) { s = ew[2 * e]; d = ew[2 * (E + e)]; }
        else      { s = ew[e];     d = ew[E + e]; }
        int pos = atomicAdd(&g_cursor[d], 1);
        float nm = g_dis[s] * g_dis[d];
        g_csr[pos] = make_int2(s, __float_as_int(nm));
    }
    // restore histogram to zero for the next call (first call: zero-init)
    for (int i = blockIdx.x * blockDim.x + threadIdx.x; i < n;
         i += gridDim.x * blockDim.x)
        g_cnt[i] = 0;
}

// =========== tensor-core GEMM: XWH = fp16(X @ W^T), bf16 split ============
// mma.sync.m16n8k16 bf16; 2-term split, 3 passes; fp32 accum. CTA 128x128.
#define GEMM_SMEM_BYTES 65536
#define AHI_OFF 0
#define ALO_OFF 16384
#define BHI_OFF 32768
#define BLO_OFF 49152

static __device__ __forceinline__ uint32_t smem_u32(const void* p) {
    uint32_t a;
    asm("{ .reg .u64 t; cvta.to.shared.u64 t, %1; cvt.u32.u64 %0, t; }"
        : "=r"(a) : "l"(p));
    return a;
}

static __device__ __forceinline__ uint32_t sw_off(int r, int c) {
    return (uint32_t)(r * 128 + (((c) << 4) ^ ((r & 7) << 4)));
}

static __device__ __forceinline__ void split_pair(float x, float y,
                                                  uint32_t& hi, uint32_t& lo) {
    __nv_bfloat162 h = __floats2bfloat162_rn(x, y);
    __nv_bfloat162 l = __floats2bfloat162_rn(x - __bfloat162float(h.x),
                                             y - __bfloat162float(h.y));
    hi = *reinterpret_cast<uint32_t*>(&h);
    lo = *reinterpret_cast<uint32_t*>(&l);
}

#define LDSM_X4(r, addr) \
    asm volatile("ldmatrix.sync.aligned.m8n8.x4.shared.b16 {%0,%1,%2,%3}, [%4];" \
                 : "=r"((r)[0]), "=r"((r)[1]), "=r"((r)[2]), "=r"((r)[3]) : "r"(addr))
#define LDSM_X2(r, addr) \
    asm volatile("ldmatrix.sync.aligned.m8n8.x2.shared.b16 {%0,%1}, [%2];" \
                 : "=r"((r)[0]), "=r"((r)[1]) : "r"(addr))
#define MMA_BF16(d, a, b) \
    asm volatile("mma.sync.aligned.m16n8k16.row.col.f32.bf16.bf16.f32 " \
                 "{%0,%1,%2,%3}, {%4,%5,%6,%7}, {%8,%9}, {%0,%1,%2,%3};" \
                 : "+f"((d)[0]), "+f"((d)[1]), "+f"((d)[2]), "+f"((d)[3]) \
                 : "r"((a)[0]), "r"((a)[1]), "r"((a)[2]), "r"((a)[3]), \
                   "r"((b)[0]), "r"((b)[1]))

__global__ void __launch_bounds__(256, 2)
gcn_gemm(const float* __restrict__ X, const float* __restrict__ W,
         __half* __restrict__ XWH, int nrows)
{
    extern __shared__ char smem[];
    const uint32_t smb = smem_u32(smem);
    const int tid = threadIdx.x;
    const int lane = tid & 31;
    const int wid = tid >> 5;
    const int warp_m = wid & 3;
    const int warp_n = wid >> 2;
    const int row0 = blockIdx.x * 128;

    float acc[2][8][4];
    #pragma unroll
    for (int mi = 0; mi < 2; mi++)
        #pragma unroll
        for (int nj = 0; nj < 8; nj++)
            #pragma unroll
            for (int q = 0; q < 4; q++) acc[mi][nj][q] = 0.f;

    const int arow = lane & 15;
    const int akh  = lane >> 4;
    const int brow = lane & 7;
    const int bkh  = (lane >> 3) & 1;

    #pragma unroll
    for (int t = 0; t < 2; t++) {
        const int k0 = t * 64;

        #pragma unroll
        for (int it = 0; it < 4; it++) {
            int id = tid + 256 * it;
            int r = id >> 3, c8 = id & 7;
            uint32_t so = sw_off(r, c8);
            int gr = row0 + r;
            float4 xa = make_float4(0.f, 0.f, 0.f, 0.f), xb = xa;
            if (gr < nrows) {
                const float4* xp = (const float4*)(X + (size_t)gr * HD + k0 + c8 * 8);
                xa = xp[0]; xb = xp[1];
            }
            uint4 hi4, lo4;
            split_pair(xa.x, xa.y, hi4.x, lo4.x);
            split_pair(xa.z, xa.w, hi4.y, lo4.y);
            split_pair(xb.x, xb.y, hi4.z, lo4.z);
            split_pair(xb.z, xb.w, hi4.w, lo4.w);
            *(uint4*)(smem + AHI_OFF + so) = hi4;
            *(uint4*)(smem + ALO_OFF + so) = lo4;
            const float4* wp = (const float4*)(W + (size_t)r * HD + k0 + c8 * 8);
            float4 wa = wp[0], wb = wp[1];
            split_pair(wa.x, wa.y, hi4.x, lo4.x);
            split_pair(wa.z, wa.w, hi4.y, lo4.y);
            split_pair(wb.x, wb.y, hi4.z, lo4.z);
            split_pair(wb.z, wb.w, hi4.w, lo4.w);
            *(uint4*)(smem + BHI_OFF + so) = hi4;
            *(uint4*)(smem + BLO_OFF + so) = lo4;
        }
        __syncthreads();

        #pragma unroll
        for (int kc = 0; kc < 4; kc++) {
            uint32_t ahi[2][4], alo[2][4];
            #pragma unroll
            for (int mi = 0; mi < 2; mi++) {
                int rr = warp_m * 32 + mi * 16 + arow;
                uint32_t off = sw_off(rr, 2 * kc + akh);
                LDSM_X4(ahi[mi], smb + AHI_OFF + off);
                LDSM_X4(alo[mi], smb + ALO_OFF + off);
            }
            #pragma unroll
            for (int nj = 0; nj < 8; nj++) {
                int nr = warp_n * 64 + nj * 8 + brow;
                uint32_t boff = sw_off(nr, 2 * kc + bkh);
                uint32_t bh[2], bl[2];
                LDSM_X2(bh, smb + BHI_OFF + boff);
                LDSM_X2(bl, smb + BLO_OFF + boff);
                #pragma unroll
                for (int mi = 0; mi < 2; mi++) {
                    MMA_BF16(acc[mi][nj], ahi[mi], bh);
                    MMA_BF16(acc[mi][nj], ahi[mi], bl);
                    MMA_BF16(acc[mi][nj], alo[mi], bh);
                }
            }
        }
        __syncthreads();
    }

    const int gr0 = lane >> 2;
    const int gc0 = (lane & 3) * 2;
    #pragma unroll
    for (int mi = 0; mi < 2; mi++) {
        #pragma unroll
        for (int nj = 0; nj < 8; nj++) {
            int cc = warp_n * 64 + nj * 8 + gc0;
            int r1 = row0 + warp_m * 32 + mi * 16 + gr0;
            if (r1 < nrows) {
                __half2 h = __floats2half2_rn(acc[mi][nj][0], acc[mi][nj][1]);
                *(__half2*)&XWH[(size_t)r1 * HD + cc] = h;
            }
            int r2 = r1 + 8;
            if (r2 < nrows) {
                __half2 h = __floats2half2_rn(acc[mi][nj][2], acc[mi][nj][3]);
                *(__half2*)&XWH[(size_t)r2 * HD + cc] = h;
            }
        }
    }
}

// ---------------- aggregation ------------------------------------------------
// out[d] = b + dis[d]^2 * xwh[d] + sum norm_e * xwh[src_e]
// Lane-parallel edge fetch: lane i holds edge beg+i, shfl-broadcast per edge;
// all gathers independent -> MLP ~= deg.
__global__ void __launch_bounds__(256)
aggregate_kernel(const float* __restrict__ bias,
                 const __half* __restrict__ xwh,
                 float* __restrict__ out, int n)
{
    int node = blockIdx.x * 8 + (threadIdx.x >> 5);
    int lane = threadIdx.x & 31;
    if (node >= n) return;

    int beg = g_rowptr[node];
    int end = g_rowptr[node + 1];
    int deg = end - beg;

    float ds = g_dis[node];
    float sc = ds * ds;
    h4 hs = ((const h4*)(xwh + (size_t)node * HD))[lane];
    float2 s0 = __half22float2(hs.a), s1 = __half22float2(hs.b);
    float4 b4 = ((const float4*)bias)[lane];
    float4 acc;
    acc.x = fmaf(sc, s0.x, b4.x);
    acc.y = fmaf(sc, s0.y, b4.y);
    acc.z = fmaf(sc, s1.x, b4.z);
    acc.w = fmaf(sc, s1.y, b4.w);

    int2 my_e = make_int2(0, 0);
    if (lane < deg) my_e = g_csr[beg + lane];
    int m = min(deg, 32);
    #pragma unroll 4
    for (int j = 0; j < m; j++) {
        int   s  = __shfl_sync(0xffffffffu, my_e.x, j);
        float nm = __int_as_float(__shfl_sync(0xffffffffu, my_e.y, j));
        h4 hv = ((const h4*)(xwh + (size_t)s * HD))[lane];
        float2 fa = __half22float2(hv.a), fb = __half22float2(hv.b);
        acc.x = fmaf(nm, fa.x, acc.x); acc.y = fmaf(nm, fa.y, acc.y);
        acc.z = fmaf(nm, fb.x, acc.z); acc.w = fmaf(nm, fb.y, acc.w);
    }
    // rare tail: deg > 32
    for (int p = beg + 32; p < end; p++) {
        int2 e = g_csr[p];
        h4 hv = ((const h4*)(xwh + (size_t)e.x * HD))[lane];
        float nm = __int_as_float(e.y);
        float2 fa = __half22float2(hv.a), fb = __half22float2(hv.b);
        acc.x = fmaf(nm, fa.x, acc.x); acc.y = fmaf(nm, fa.y, acc.y);
        acc.z = fmaf(nm, fb.x, acc.z); acc.w = fmaf(nm, fb.y, acc.w);
    }

    ((float4*)(out + (size_t)node * HD))[lane] = acc;
}

// ---------------- launch ----------------------------------------------------
extern "C" void kernel_launch(void* const* d_in, const int* in_sizes, int n_in,
                              void* d_out, int out_size) {
    const float* emb = (const float*)d_in[0];
    const int*   ew  = (const int*)d_in[1];   // width detected on device
    const float* W1  = (const float*)d_in[2];
    const float* b1  = (const float*)d_in[3];
    const float* W2  = (const float*)d_in[4];
    const float* b2  = (const float*)d_in[5];
    float* out = (float*)d_out;

    const int nrows = in_sizes[0] / HD;       // 50000
    const int E     = in_sizes[1] / 2;        // 600000

    float* h1_p;
    __half* xwh_p;
    cudaGetSymbolAddress((void**)&xwh_p, g_xwh);
    cudaGetSymbolAddress((void**)&h1_p,  g_h1);

    cudaFuncSetAttribute(gcn_gemm, cudaFuncAttributeMaxDynamicSharedMemorySize,
                         GEMM_SMEM_BYTES);

    // Side stream + events (created once on the first, non-captured call).
    static cudaStream_t s_side = nullptr;
    static cudaEvent_t  s_ev0 = nullptr, s_ev1 = nullptr;
    if (s_side == nullptr) {
        cudaStreamCreateWithFlags(&s_side, cudaStreamNonBlocking);
        cudaEventCreateWithFlags(&s_ev0, cudaEventDisableTiming);
        cudaEventCreateWithFlags(&s_ev1, cudaEventDisableTiming);
    }

    const int nb_nodes = (nrows + 255) / 256;   // 196
    const int nb_edges = (E + 255) / 256;       // 2344
    const int nb_gemm  = (nrows + 127) / 128;   // 391
    const int nb_agg   = (nrows + 7) / 8;       // 6250

    // ---- fork: layer-1 GEMM on side stream, CSR build on main stream ----
    cudaEventRecord(s_ev0, 0);
    cudaStreamWaitEvent(s_side, s_ev0, 0);
    gcn_gemm<<<nb_gemm, 256, GEMM_SMEM_BYTES, s_side>>>(emb, W1, xwh_p, nrows);
    cudaEventRecord(s_ev1, s_side);

    hist_kernel<<<nb_edges, 256>>>(ew, E);
    scanA_kernel<<<nb_nodes, 256>>>(nrows);
    scanB_kernel<<<1, 256>>>(nb_nodes);
    scanC_kernel<<<nb_nodes, 256>>>(nrows, E);
    fill_kernel<<<nb_edges, 256>>>(ew, E, nrows);

    // ---- join, then serial tail ----
    cudaStreamWaitEvent(0, s_ev1, 0);
    aggregate_kernel<<<nb_agg, 256>>>(b1, xwh_p, h1_p, nrows);
    gcn_gemm<<<nb_gemm, 256, GEMM_SMEM_BYTES>>>(h1_p, W2, xwh_p, nrows);
    aggregate_kernel<<<nb_agg, 256>>>(b2, xwh_p, out, nrows);
}

// round 14
// speedup vs baseline: 1.0307x; 1.0307x over previous
#include <cuda_runtime.h>
#include <cuda_fp16.h>
#include <cuda_bf16.h>
#include <cstdint>

#define N_NODES 50000
#define HD 128
#define E_MAX 600000

// ---------------- scratch (device globals; no dynamic allocation) ----------
__device__ float  g_dis[N_NODES];                 // rsqrt(degree incl. self-loop)
__device__ int    g_cnt[N_NODES];                 // in-degree histogram
__device__ int2   g_seg[N_NODES];                 // (beg, deg) of each node's segment
__device__ int    g_cursor[N_NODES];              // fill cursors
__device__ int    g_total;                        // ticket counter (reset by fill)
__device__ int2   g_csr[E_MAX];                   // packed (src, norm), segment-grouped
__device__ __half g_xwh[(size_t)N_NODES * HD];    // x @ W^T (fp16)
__device__ float  g_h1[(size_t)N_NODES * HD];     // layer-1 output (fp32)
__device__ int    g_is64;                         // 1 if edge_index stored as int64

struct __align__(8) h4 { __half2 a, b; };

// ---------------- init + dtype detect (merged) ------------------------------
// Block 0 detects index width: int64 little-endian => odd 32-bit words of the
// first 2048 logical elements are all zero (random int32 indices make that
// impossible). Reads stay in-bounds for both interpretations.
__global__ void initdetect_kernel(const int* __restrict__ ew, int n) {
    int i = blockIdx.x * blockDim.x + threadIdx.x;
    if (i < n) g_cnt[i] = 0;
    if (blockIdx.x == 0) {
        __shared__ int found;
        if (threadIdx.x == 0) found = 0;
        __syncthreads();
        int f = 0;
        for (int j = threadIdx.x; j < 2048; j += blockDim.x)
            if (ew[2 * j + 1] != 0) f = 1;
        if (f) atomicOr(&found, 1);
        __syncthreads();
        if (threadIdx.x == 0) g_is64 = found ? 0 : 1;
    }
}

__global__ void hist_kernel(const int* __restrict__ ew, int E) {
    int e = blockIdx.x * blockDim.x + threadIdx.x;
    if (e >= E) return;
    int d = g_is64 ? ew[2 * (E + e)] : ew[E + e];
    atomicAdd(&g_cnt[d], 1);
}

// ---- single-launch segment assignment (ticket scan) ------------------------
// Canonical prefix order is NOT required: each block reserves space for its
// 256 nodes via one atomicAdd; segments land in arbitrary order. Emits
// (beg, deg), cursor and dis.
__global__ void scanM_kernel(int n) {
    __shared__ int sm[256];
    __shared__ int base_sh;
    int i = blockIdx.x * 256 + threadIdx.x;
    int v = (i < n) ? g_cnt[i] : 0;
    if (i < n) g_dis[i] = rsqrtf((float)(v + 1));
    sm[threadIdx.x] = v;
    __syncthreads();
    #pragma unroll
    for (int off = 1; off < 256; off <<= 1) {
        int t = (threadIdx.x >= off) ? sm[threadIdx.x - off] : 0;
        __syncthreads();
        sm[threadIdx.x] += t;
        __syncthreads();
    }
    if (threadIdx.x == 255) base_sh = atomicAdd(&g_total, sm[255]);
    __syncthreads();
    if (i < n) {
        int beg = base_sh + sm[threadIdx.x] - v;
        g_seg[i] = make_int2(beg, v);
        g_cursor[i] = beg;
    }
}

__global__ void fill_kernel(const int* __restrict__ ew, int E) {
    // reset ticket counter for the next call/replay (scan has fully completed)
    if (blockIdx.x == 0 && threadIdx.x == 0) g_total = 0;
    int e = blockIdx.x * blockDim.x + threadIdx.x;
    if (e >= E) return;
    int s, d;
    if (g_is64) { s = ew[2 * e]; d = ew[2 * (E + e)]; }
    else        { s = ew[e];     d = ew[E + e]; }
    int pos = atomicAdd(&g_cursor[d], 1);
    float nm = g_dis[s] * g_dis[d];
    g_csr[pos] = make_int2(s, __float_as_int(nm));
}

// =========== tensor-core GEMM: XWH = fp16(X @ W^T), bf16 split ============
// mma.sync.m16n8k16 bf16; 2-term split, 3 passes; fp32 accum. CTA 128x128.
#define GEMM_SMEM_BYTES 65536
#define AHI_OFF 0
#define ALO_OFF 16384
#define BHI_OFF 32768
#define BLO_OFF 49152

static __device__ __forceinline__ uint32_t smem_u32(const void* p) {
    uint32_t a;
    asm("{ .reg .u64 t; cvta.to.shared.u64 t, %1; cvt.u32.u64 %0, t; }"
        : "=r"(a) : "l"(p));
    return a;
}

static __device__ __forceinline__ uint32_t sw_off(int r, int c) {
    return (uint32_t)(r * 128 + (((c) << 4) ^ ((r & 7) << 4)));
}

static __device__ __forceinline__ void split_pair(float x, float y,
                                                  uint32_t& hi, uint32_t& lo) {
    __nv_bfloat162 h = __floats2bfloat162_rn(x, y);
    __nv_bfloat162 l = __floats2bfloat162_rn(x - __bfloat162float(h.x),
                                             y - __bfloat162float(h.y));
    hi = *reinterpret_cast<uint32_t*>(&h);
    lo = *reinterpret_cast<uint32_t*>(&l);
}

#define LDSM_X4(r, addr) \
    asm volatile("ldmatrix.sync.aligned.m8n8.x4.shared.b16 {%0,%1,%2,%3}, [%4];" \
                 : "=r"((r)[0]), "=r"((r)[1]), "=r"((r)[2]), "=r"((r)[3]) : "r"(addr))
#define LDSM_X2(r, addr) \
    asm volatile("ldmatrix.sync.aligned.m8n8.x2.shared.b16 {%0,%1}, [%2];" \
                 : "=r"((r)[0]), "=r"((r)[1]) : "r"(addr))
#define MMA_BF16(d, a, b) \
    asm volatile("mma.sync.aligned.m16n8k16.row.col.f32.bf16.bf16.f32 " \
                 "{%0,%1,%2,%3}, {%4,%5,%6,%7}, {%8,%9}, {%0,%1,%2,%3};" \
                 : "+f"((d)[0]), "+f"((d)[1]), "+f"((d)[2]), "+f"((d)[3]) \
                 : "r"((a)[0]), "r"((a)[1]), "r"((a)[2]), "r"((a)[3]), \
                   "r"((b)[0]), "r"((b)[1]))

__global__ void __launch_bounds__(256, 2)
gcn_gemm(const float* __restrict__ X, const float* __restrict__ W,
         __half* __restrict__ XWH, int nrows)
{
    extern __shared__ char smem[];
    const uint32_t smb = smem_u32(smem);
    const int tid = threadIdx.x;
    const int lane = tid & 31;
    const int wid = tid >> 5;
    const int warp_m = wid & 3;
    const int warp_n = wid >> 2;
    const int row0 = blockIdx.x * 128;

    float acc[2][8][4];
    #pragma unroll
    for (int mi = 0; mi < 2; mi++)
        #pragma unroll
        for (int nj = 0; nj < 8; nj++)
            #pragma unroll
            for (int q = 0; q < 4; q++) acc[mi][nj][q] = 0.f;

    const int arow = lane & 15;
    const int akh  = lane >> 4;
    const int brow = lane & 7;
    const int bkh  = (lane >> 3) & 1;

    #pragma unroll
    for (int t = 0; t < 2; t++) {
        const int k0 = t * 64;

        #pragma unroll
        for (int it = 0; it < 4; it++) {
            int id = tid + 256 * it;
            int r = id >> 3, c8 = id & 7;
            uint32_t so = sw_off(r, c8);
            int gr = row0 + r;
            float4 xa = make_float4(0.f, 0.f, 0.f, 0.f), xb = xa;
            if (gr < nrows) {
                const float4* xp = (const float4*)(X + (size_t)gr * HD + k0 + c8 * 8);
                xa = xp[0]; xb = xp[1];
            }
            uint4 hi4, lo4;
            split_pair(xa.x, xa.y, hi4.x, lo4.x);
            split_pair(xa.z, xa.w, hi4.y, lo4.y);
            split_pair(xb.x, xb.y, hi4.z, lo4.z);
            split_pair(xb.z, xb.w, hi4.w, lo4.w);
            *(uint4*)(smem + AHI_OFF + so) = hi4;
            *(uint4*)(smem + ALO_OFF + so) = lo4;
            const float4* wp = (const float4*)(W + (size_t)r * HD + k0 + c8 * 8);
            float4 wa = wp[0], wb = wp[1];
            split_pair(wa.x, wa.y, hi4.x, lo4.x);
            split_pair(wa.z, wa.w, hi4.y, lo4.y);
            split_pair(wb.x, wb.y, hi4.z, lo4.z);
            split_pair(wb.z, wb.w, hi4.w, lo4.w);
            *(uint4*)(smem + BHI_OFF + so) = hi4;
            *(uint4*)(smem + BLO_OFF + so) = lo4;
        }
        __syncthreads();

        #pragma unroll
        for (int kc = 0; kc < 4; kc++) {
            uint32_t ahi[2][4], alo[2][4];
            #pragma unroll
            for (int mi = 0; mi < 2; mi++) {
                int rr = warp_m * 32 + mi * 16 + arow;
                uint32_t off = sw_off(rr, 2 * kc + akh);
                LDSM_X4(ahi[mi], smb + AHI_OFF + off);
                LDSM_X4(alo[mi], smb + ALO_OFF + off);
            }
            #pragma unroll
            for (int nj = 0; nj < 8; nj++) {
                int nr = warp_n * 64 + nj * 8 + brow;
                uint32_t boff = sw_off(nr, 2 * kc + bkh);
                uint32_t bh[2], bl[2];
                LDSM_X2(bh, smb + BHI_OFF + boff);
                LDSM_X2(bl, smb + BLO_OFF + boff);
                #pragma unroll
                for (int mi = 0; mi < 2; mi++) {
                    MMA_BF16(acc[mi][nj], ahi[mi], bh);
                    MMA_BF16(acc[mi][nj], ahi[mi], bl);
                    MMA_BF16(acc[mi][nj], alo[mi], bh);
                }
            }
        }
        __syncthreads();
    }

    const int gr0 = lane >> 2;
    const int gc0 = (lane & 3) * 2;
    #pragma unroll
    for (int mi = 0; mi < 2; mi++) {
        #pragma unroll
        for (int nj = 0; nj < 8; nj++) {
            int cc = warp_n * 64 + nj * 8 + gc0;
            int r1 = row0 + warp_m * 32 + mi * 16 + gr0;
            if (r1 < nrows) {
                __half2 h = __floats2half2_rn(acc[mi][nj][0], acc[mi][nj][1]);
                *(__half2*)&XWH[(size_t)r1 * HD + cc] = h;
            }
            int r2 = r1 + 8;
            if (r2 < nrows) {
                __half2 h = __floats2half2_rn(acc[mi][nj][2], acc[mi][nj][3]);
                *(__half2*)&XWH[(size_t)r2 * HD + cc] = h;
            }
        }
    }
}

// ---------------- aggregation ------------------------------------------------
// out[d] = b + dis[d]^2 * xwh[d] + sum norm_e * xwh[src_e]   (fp16 gathers)
__global__ void __launch_bounds__(256)
aggregate_kernel(const float* __restrict__ bias,
                 const __half* __restrict__ xwh,
                 float* __restrict__ out, int n)
{
    int node = blockIdx.x * 8 + (threadIdx.x >> 5);
    int lane = threadIdx.x & 31;
    if (node >= n) return;

    int2 seg = g_seg[node];
    int beg = seg.x;
    int end = seg.x + seg.y;

    float ds = g_dis[node];
    float sc = ds * ds;
    h4 hs = ((const h4*)(xwh + (size_t)node * HD))[lane];
    float2 s0 = __half22float2(hs.a), s1 = __half22float2(hs.b);
    float4 b4 = ((const float4*)bias)[lane];
    float4 acc;
    acc.x = fmaf(sc, s0.x, b4.x);
    acc.y = fmaf(sc, s0.y, b4.y);
    acc.z = fmaf(sc, s1.x, b4.z);
    acc.w = fmaf(sc, s1.y, b4.w);

    int p = beg;
    for (; p + 4 <= end; p += 4) {
        int2 e0 = g_csr[p + 0];
        int2 e1 = g_csr[p + 1];
        int2 e2 = g_csr[p + 2];
        int2 e3 = g_csr[p + 3];
        h4 h0 = ((const h4*)(xwh + (size_t)e0.x * HD))[lane];
        h4 h1 = ((const h4*)(xwh + (size_t)e1.x * HD))[lane];
        h4 h2 = ((const h4*)(xwh + (size_t)e2.x * HD))[lane];
        h4 h3 = ((const h4*)(xwh + (size_t)e3.x * HD))[lane];
        float n0 = __int_as_float(e0.y), n1 = __int_as_float(e1.y);
        float n2 = __int_as_float(e2.y), n3 = __int_as_float(e3.y);
        float2 a0 = __half22float2(h0.a), b0 = __half22float2(h0.b);
        float2 a1 = __half22float2(h1.a), b1 = __half22float2(h1.b);
        float2 a2 = __half22float2(h2.a), b2 = __half22float2(h2.b);
        float2 a3 = __half22float2(h3.a), b3 = __half22float2(h3.b);
        acc.x = fmaf(n0, a0.x, acc.x); acc.y = fmaf(n0, a0.y, acc.y);
        acc.z = fmaf(n0, b0.x, acc.z); acc.w = fmaf(n0, b0.y, acc.w);
        acc.x = fmaf(n1, a1.x, acc.x); acc.y = fmaf(n1, a1.y, acc.y);
        acc.z = fmaf(n1, b1.x, acc.z); acc.w = fmaf(n1, b1.y, acc.w);
        acc.x = fmaf(n2, a2.x, acc.x); acc.y = fmaf(n2, a2.y, acc.y);
        acc.z = fmaf(n2, b2.x, acc.z); acc.w = fmaf(n2, b2.y, acc.w);
        acc.x = fmaf(n3, a3.x, acc.x); acc.y = fmaf(n3, a3.y, acc.y);
        acc.z = fmaf(n3, b3.x, acc.z); acc.w = fmaf(n3, b3.y, acc.w);
    }
    for (; p < end; p++) {
        int2 e = g_csr[p];
        h4 hv = ((const h4*)(xwh + (size_t)e.x * HD))[lane];
        float nm = __int_as_float(e.y);
        float2 fa = __half22float2(hv.a), fb = __half22float2(hv.b);
        acc.x = fmaf(nm, fa.x, acc.x); acc.y = fmaf(nm, fa.y, acc.y);
        acc.z = fmaf(nm, fb.x, acc.z); acc.w = fmaf(nm, fb.y, acc.w);
    }

    ((float4*)(out + (size_t)node * HD))[lane] = acc;
}

// ---------------- launch ----------------------------------------------------
extern "C" void kernel_launch(void* const* d_in, const int* in_sizes, int n_in,
                              void* d_out, int out_size) {
    const float* emb = (const float*)d_in[0];
    const int*   ew  = (const int*)d_in[1];   // width detected on device
    const float* W1  = (const float*)d_in[2];
    const float* b1  = (const float*)d_in[3];
    const float* W2  = (const float*)d_in[4];
    const float* b2  = (const float*)d_in[5];
    float* out = (float*)d_out;

    const int nrows = in_sizes[0] / HD;       // 50000
    const int E     = in_sizes[1] / 2;        // 600000

    float* h1_p;
    __half* xwh_p;
    cudaGetSymbolAddress((void**)&xwh_p, g_xwh);
    cudaGetSymbolAddress((void**)&h1_p,  g_h1);

    cudaFuncSetAttribute(gcn_gemm, cudaFuncAttributeMaxDynamicSharedMemorySize,
                         GEMM_SMEM_BYTES);

    // Side stream + events (created once on the first, non-captured call).
    static cudaStream_t s_side = nullptr;
    static cudaEvent_t  s_ev0 = nullptr, s_ev1 = nullptr;
    if (s_side == nullptr) {
        cudaStreamCreateWithFlags(&s_side, cudaStreamNonBlocking);
        cudaEventCreateWithFlags(&s_ev0, cudaEventDisableTiming);
        cudaEventCreateWithFlags(&s_ev1, cudaEventDisableTiming);
    }

    const int nb_nodes = (nrows + 255) / 256;   // 196
    const int nb_edges = (E + 255) / 256;       // 2344
    const int nb_gemm  = (nrows + 127) / 128;   // 391
    const int nb_agg   = (nrows + 7) / 8;       // 6250

    // ---- fork: layer-1 GEMM on side stream, CSR build on main stream ----
    cudaEventRecord(s_ev0, 0);
    cudaStreamWaitEvent(s_side, s_ev0, 0);
    gcn_gemm<<<nb_gemm, 256, GEMM_SMEM_BYTES, s_side>>>(emb, W1, xwh_p, nrows);
    cudaEventRecord(s_ev1, s_side);

    initdetect_kernel<<<nb_nodes, 256>>>(ew, nrows);
    hist_kernel<<<nb_edges, 256>>>(ew, E);
    scanM_kernel<<<nb_nodes, 256>>>(nrows);
    fill_kernel<<<nb_edges, 256>>>(ew, E);

    // ---- join, then serial tail ----
    cudaStreamWaitEvent(0, s_ev1, 0);
    aggregate_kernel<<<nb_agg, 256>>>(b1, xwh_p, h1_p, nrows);
    gcn_gemm<<<nb_gemm, 256, GEMM_SMEM_BYTES>>>(h1_p, W2, xwh_p, nrows);
    aggregate_kernel<<<nb_agg, 256>>>(b2, xwh_p, out, nrows);
}